// round 7
// baseline (speedup 1.0000x reference)
// HRALinear on GB300 (compute_103 non-'a' toolchain => NO tcgen05/TMA).
// Path: compact-WY Householder prep + Ampere-style tf32 mma.sync GEMM.
//
//   P0: x  -> g_Xr  (cvt.rna.tf32 pre-round, so HW mma truncation == RN)
//   P1: normalize u cols -> g_UT; Gram; WY T matrix (8x8)
//   P2: W' = W - (W U) T U^T, tf32-RN-rounded into g_Wp
//   G : out = x @ W'^T + bias
//        mma.sync.m16n8k8.tf32, CTA tile 128x128, K-chunk 32,
//        3-stage cp.async pipeline, padded SMEM (row stride 36 floats ->
//        fragment LDS bank = (4g+tig)%32, a perfect permutation).

#include <cuda_runtime.h>
#include <cstdint>

#define DIN  4096
#define DOUT 4096
#define RNK  8
#define MTOT 8192   // 4 * 2048 rows of x

// ---- static device scratch (allocation-free) ----
__device__ float g_UT[RNK * DIN];            // normalized u^T [8][4096]
__device__ float g_T[64];                    // WY T matrix
__device__ float g_Wp[(size_t)DOUT * DIN];   // W' (tf32-rounded), 64 MB
__device__ float g_Xr[(size_t)MTOT * DIN];   // x  (tf32-rounded), 128 MB

// ============================ helpers ============================

static __device__ __forceinline__ uint32_t smem_u32(const void* p) {
    uint32_t a;
    asm("{ .reg .u64 t; cvta.to.shared.u64 t, %1; cvt.u32.u64 %0, t; }"
        : "=r"(a) : "l"(p));
    return a;
}

static __device__ __forceinline__ uint32_t tf32r(float f) {
    uint32_t u;
    asm("cvt.rna.tf32.f32 %0, %1;" : "=r"(u) : "f"(f));
    return u;
}

// ============================ P0: round x to tf32 ============================

__global__ void __launch_bounds__(256)
p0_round(const float* __restrict__ x) {
    size_t i = ((size_t)blockIdx.x * 256 + threadIdx.x) * 4;
    float4 v = *(const float4*)(x + i);
    uint4 u;
    u.x = tf32r(v.x); u.y = tf32r(v.y); u.z = tf32r(v.z); u.w = tf32r(v.w);
    *(uint4*)(g_Xr + i) = u;
}

// ============================ P1: normalize + Gram + T ============================

__global__ void __launch_bounds__(512)
p1_kernel(const float* __restrict__ hu) {
    __shared__ float s_rn[8];
    __shared__ float s_G[64];
    const int tid = threadIdx.x, wid = tid >> 5, lid = tid & 31;

    if (wid < 8) {
        float s = 0.f;
        for (int k = lid; k < DIN; k += 32) {
            float v = hu[(size_t)k * RNK + wid];
            s += v * v;
        }
        #pragma unroll
        for (int o = 16; o; o >>= 1) s += __shfl_xor_sync(0xFFFFFFFFu, s, o);
        if (lid == 0) s_rn[wid] = rsqrtf(s);
    }
    __syncthreads();

    for (int idx = tid; idx < RNK * DIN; idx += 512) {
        int i = idx >> 12, k = idx & (DIN - 1);
        g_UT[idx] = hu[(size_t)k * RNK + i] * s_rn[i];
    }
    __syncthreads();

    // Gram over the 36 (i<=j) pairs, one warp per pair (strided).
    for (int p = wid; p < 36; p += 16) {
        int i = 0, rem = p;
        while (rem >= RNK - i) { rem -= RNK - i; i++; }
        int jj = i + rem;
        float s = 0.f;
        for (int k = lid; k < DIN; k += 32)
            s += g_UT[i * DIN + k] * g_UT[jj * DIN + k];
        #pragma unroll
        for (int o = 16; o; o >>= 1) s += __shfl_xor_sync(0xFFFFFFFFu, s, o);
        if (lid == 0) { s_G[i * 8 + jj] = s; s_G[jj * 8 + i] = s; }
    }
    __syncthreads();

    // WY: H0..H7 = I - U T U^T ; T_{k+1} = [[T_k, -2 T_k g_k],[0, 2]]
    if (tid == 0) {
        float T[64];
        #pragma unroll
        for (int m = 0; m < 64; m++) T[m] = 0.f;
        T[0] = 2.f;
        for (int k = 1; k < 8; k++) {
            for (int i = 0; i < k; i++) {
                float s = 0.f;
                for (int m2 = i; m2 < k; m2++) s += T[i * 8 + m2] * s_G[m2 * 8 + k];
                T[i * 8 + k] = -2.f * s;
            }
            T[k * 8 + k] = 2.f;
        }
        for (int m = 0; m < 64; m++) g_T[m] = T[m];
    }
}

// ============================ P2: W' = W - (W U) T U^T ============================

static constexpr int P2_SMEM = (RNK * DIN + 64) * 4;

__global__ void __launch_bounds__(256)
p2_kernel(const float* __restrict__ W) {
    extern __shared__ float s[];
    float* sUT = s;
    float* sT  = s + RNK * DIN;
    const int tid = threadIdx.x;

    for (int idx = tid * 4; idx < RNK * DIN; idx += 256 * 4)
        *(float4*)(sUT + idx) = *(const float4*)(g_UT + idx);
    if (tid < 64) sT[tid] = g_T[tid];
    __syncthreads();

    const int wid = tid >> 5, lid = tid & 31;
    const int j = blockIdx.x * 8 + wid;          // one W row per warp
    const float* wr = W + (size_t)j * DIN;

    float acc[8] = {0.f, 0.f, 0.f, 0.f, 0.f, 0.f, 0.f, 0.f};
    for (int k = lid * 4; k < DIN; k += 128) {
        float4 w4 = *(const float4*)(wr + k);
        #pragma unroll
        for (int i = 0; i < 8; i++) {
            float4 u4 = *(const float4*)(sUT + i * DIN + k);
            acc[i] += w4.x * u4.x + w4.y * u4.y + w4.z * u4.z + w4.w * u4.w;
        }
    }
    #pragma unroll
    for (int o = 16; o; o >>= 1) {
        #pragma unroll
        for (int i = 0; i < 8; i++)
            acc[i] += __shfl_xor_sync(0xFFFFFFFFu, acc[i], o);
    }
    float v[8];
    #pragma unroll
    for (int i = 0; i < 8; i++) {
        float sv = 0.f;
        #pragma unroll
        for (int m = 0; m < 8; m++) sv += acc[m] * sT[m * 8 + i];
        v[i] = sv;
    }

    float* wp = g_Wp + (size_t)j * DIN;
    for (int k = lid * 4; k < DIN; k += 128) {
        float4 w4 = *(const float4*)(wr + k);
        #pragma unroll
        for (int i = 0; i < 8; i++) {
            float4 u4 = *(const float4*)(sUT + i * DIN + k);
            w4.x -= v[i] * u4.x; w4.y -= v[i] * u4.y;
            w4.z -= v[i] * u4.z; w4.w -= v[i] * u4.w;
        }
        uint4 r;                                  // round W' to tf32 (RN)
        r.x = tf32r(w4.x); r.y = tf32r(w4.y);
        r.z = tf32r(w4.z); r.w = tf32r(w4.w);
        *(uint4*)(wp + k) = r;
    }
}

// ============================ GEMM: out = Xr @ Wp^T + bias ============================

static constexpr int BM = 128, BN = 128, BK = 32, STG = 3;
static constexpr int ROWF    = 36;                 // padded row stride (floats)
static constexpr int AS_F    = BM * ROWF;          // 4608 floats per A stage
static constexpr int STAGE_F = 2 * AS_F;           // 9216 floats (A + B)
static constexpr int GEMM_SMEM = STG * STAGE_F * 4; // 110592 B

// Issue one stage's cp.async (A 128x32 + B 128x32, 8 x 16B per thread).
static __device__ __forceinline__ void issue_stage(const float* gA, const float* gB,
                                                   int kc, int s, uint32_t sb, int tid) {
    uint32_t base = sb + (uint32_t)s * (STAGE_F * 4);
    #pragma unroll
    for (int j = 0; j < 4; j++) {
        int idx = tid + j * 256;
        int r = idx >> 3, c = idx & 7;
        uint32_t dA = base + (uint32_t)(r * (ROWF * 4) + c * 16);
        const float* sA = gA + (size_t)r * DIN + kc + c * 4;
        asm volatile("cp.async.cg.shared.global [%0], [%1], 16;"
                     :: "r"(dA), "l"(sA));
        uint32_t dB = base + (uint32_t)(AS_F * 4 + r * (ROWF * 4) + c * 16);
        const float* sB = gB + (size_t)r * DIN + kc + c * 4;
        asm volatile("cp.async.cg.shared.global [%0], [%1], 16;"
                     :: "r"(dB), "l"(sB));
    }
}

#define MMA_TF32(D, A, B) \
    asm volatile("mma.sync.aligned.m16n8k8.row.col.f32.tf32.tf32.f32 " \
                 "{%0,%1,%2,%3}, {%4,%5,%6,%7}, {%8,%9}, {%0,%1,%2,%3};" \
                 : "+f"((D)[0]), "+f"((D)[1]), "+f"((D)[2]), "+f"((D)[3]) \
                 : "r"((A)[0]), "r"((A)[1]), "r"((A)[2]), "r"((A)[3]), \
                   "r"((B)[0]), "r"((B)[1]))

__global__ void __launch_bounds__(256, 2)
gemm_tf32(const float* __restrict__ bias, float* __restrict__ out) {
    extern __shared__ float smf[];
    const uint32_t sb = smem_u32(smf);
    const int tid = threadIdx.x, lane = tid & 31, warp = tid >> 5;
    const int g = lane >> 2, tig = lane & 3;
    const int wm = warp >> 2, wn = warp & 3;        // 2 x 4 warp grid
    const int m0 = blockIdx.y * BM, n0 = blockIdx.x * BN;

    const float* gA = g_Xr + (size_t)m0 * DIN;
    const float* gB = g_Wp + (size_t)n0 * DIN;

    issue_stage(gA, gB, 0, 0, sb, tid);
    asm volatile("cp.async.commit_group;" ::: "memory");
    issue_stage(gA, gB, BK, 1, sb, tid);
    asm volatile("cp.async.commit_group;" ::: "memory");

    float acc[4][4][4];
    #pragma unroll
    for (int mi = 0; mi < 4; mi++)
        #pragma unroll
        for (int ni = 0; ni < 4; ni++)
            #pragma unroll
            for (int q = 0; q < 4; q++) acc[mi][ni][q] = 0.f;

    const int NCH = DIN / BK;                       // 128 K-chunks
    for (int c = 0; c < NCH; c++) {
        asm volatile("cp.async.wait_group 1;" ::: "memory");
        __syncthreads();
        if (c + 2 < NCH) issue_stage(gA, gB, (c + 2) * BK, (c + 2) % STG, sb, tid);
        asm volatile("cp.async.commit_group;" ::: "memory");

        const float* As = smf + (c % STG) * STAGE_F;
        const float* Bs = As + AS_F;

        #pragma unroll
        for (int kk = 0; kk < 4; kk++) {
            uint32_t a[4][4], b[4][2];
            #pragma unroll
            for (int mi = 0; mi < 4; mi++) {
                const int r0 = wm * 64 + mi * 16 + g;
                const int cb = kk * 8 + tig;
                a[mi][0] = __float_as_uint(As[r0 * ROWF + cb]);
                a[mi][1] = __float_as_uint(As[(r0 + 8) * ROWF + cb]);
                a[mi][2] = __float_as_uint(As[r0 * ROWF + cb + 4]);
                a[mi][3] = __float_as_uint(As[(r0 + 8) * ROWF + cb + 4]);
            }
            #pragma unroll
            for (int ni = 0; ni < 4; ni++) {
                const int n = wn * 32 + ni * 8 + g;
                b[ni][0] = __float_as_uint(Bs[n * ROWF + kk * 8 + tig]);
                b[ni][1] = __float_as_uint(Bs[n * ROWF + kk * 8 + tig + 4]);
            }
            #pragma unroll
            for (int mi = 0; mi < 4; mi++)
                #pragma unroll
                for (int ni = 0; ni < 4; ni++)
                    MMA_TF32(acc[mi][ni], a[mi], b[ni]);
        }
    }

    // Epilogue: direct STG.64 per (row, 2-col) pair + bias.
    #pragma unroll
    for (int mi = 0; mi < 4; mi++) {
        const int row = m0 + wm * 64 + mi * 16 + g;
        #pragma unroll
        for (int ni = 0; ni < 4; ni++) {
            const int col = n0 + wn * 32 + ni * 8 + 2 * tig;
            const float2 bv = *(const float2*)(bias + col);
            float2 o0, o1;
            o0.x = acc[mi][ni][0] + bv.x; o0.y = acc[mi][ni][1] + bv.y;
            o1.x = acc[mi][ni][2] + bv.x; o1.y = acc[mi][ni][3] + bv.y;
            *(float2*)(out + (size_t)row * DOUT + col) = o0;
            *(float2*)(out + (size_t)(row + 8) * DOUT + col) = o1;
        }
    }
}

// ============================ launch ============================

extern "C" void kernel_launch(void* const* d_in, const int* in_sizes, int n_in,
                              void* d_out, int out_size) {
    const float* x    = (const float*)d_in[0];  // [4, 2048, 4096]
    const float* hu   = (const float*)d_in[1];  // [4096, 8]
    const float* W    = (const float*)d_in[2];  // [4096, 4096]
    const float* bias = (const float*)d_in[3];  // [4096]
    float* out = (float*)d_out;                 // [4, 2048, 4096]
    (void)in_sizes; (void)n_in; (void)out_size;

    cudaFuncSetAttribute(p2_kernel, cudaFuncAttributeMaxDynamicSharedMemorySize, P2_SMEM);
    cudaFuncSetAttribute(gemm_tf32, cudaFuncAttributeMaxDynamicSharedMemorySize, GEMM_SMEM);

    p0_round<<<(MTOT * DIN) / (256 * 4), 256>>>(x);
    p1_kernel<<<1, 512>>>(hu);
    p2_kernel<<<512, 256, P2_SMEM>>>(W);
    gemm_tf32<<<dim3(DOUT / BN, MTOT / BM), 256, GEMM_SMEM>>>(bias, out);
}